// round 1
// baseline (speedup 1.0000x reference)
#include <cuda_runtime.h>

// Problem constants
#define BATCH   4
#define SEQ     4096
#define DMODEL  1024
#define HEAD    64
#define BT      (BATCH * SEQ)          // 16384 rows

// Scratch for projected q, k, v (allocation-free rule: __device__ globals)
__device__ float g_q[BT * HEAD];
__device__ float g_k[BT * HEAD];
__device__ float g_v[BT * HEAD];

// ---------------------------------------------------------------------------
// Projection GEMM: out = x @ W + b
// x: (BT, DMODEL) row-major; W: (DMODEL, HEAD) row-major; out: (BT, HEAD)
// Tile: BM=64, BN=64(=HEAD), BK=32. 256 threads, 4x4 micro-tile per thread.
// blockIdx.y in {0,1,2} selects q/k/v.
// ---------------------------------------------------------------------------
__global__ __launch_bounds__(256) void proj_kernel(
    const float* __restrict__ x,
    const float* __restrict__ Wq, const float* __restrict__ bq,
    const float* __restrict__ Wk, const float* __restrict__ bk,
    const float* __restrict__ Wv, const float* __restrict__ bv)
{
    const int sel = blockIdx.y;
    const float* __restrict__ W    = (sel == 0) ? Wq : (sel == 1) ? Wk : Wv;
    const float* __restrict__ bias = (sel == 0) ? bq : (sel == 1) ? bk : bv;
    float* __restrict__ out        = (sel == 0) ? g_q : (sel == 1) ? g_k : g_v;

    __shared__ float Xs[64][33];   // [m][k], pad to keep per-k column reads conflict-free
    __shared__ float Ws[32][64];   // [k][n]

    const int t  = threadIdx.x;
    const int tx = t & 15;         // output col group
    const int ty = t >> 4;         // output row group
    const int m0 = blockIdx.x * 64;

    float acc[4][4] = {};

    for (int k0 = 0; k0 < DMODEL; k0 += 32) {
        // Load X tile 64x32 (coalesced: 32 consecutive k per warp-row)
        #pragma unroll
        for (int i = t; i < 64 * 32; i += 256) {
            int r = i >> 5, k = i & 31;
            Xs[r][k] = x[(size_t)(m0 + r) * DMODEL + k0 + k];
        }
        // Load W tile 32x64 (coalesced rows)
        #pragma unroll
        for (int i = t; i < 32 * 64; i += 256) {
            int k = i >> 6, n = i & 63;
            Ws[k][n] = W[(size_t)(k0 + k) * HEAD + n];
        }
        __syncthreads();

        #pragma unroll 8
        for (int k = 0; k < 32; k++) {
            float xv[4], wv[4];
            #pragma unroll
            for (int i = 0; i < 4; i++) xv[i] = Xs[ty * 4 + i][k];
            #pragma unroll
            for (int j = 0; j < 4; j++) wv[j] = Ws[k][tx * 4 + j];
            #pragma unroll
            for (int i = 0; i < 4; i++)
                #pragma unroll
                for (int j = 0; j < 4; j++)
                    acc[i][j] += xv[i] * wv[j];
        }
        __syncthreads();
    }

    #pragma unroll
    for (int i = 0; i < 4; i++) {
        int r = m0 + ty * 4 + i;
        #pragma unroll
        for (int j = 0; j < 4; j++) {
            int c = tx * 4 + j;
            out[(size_t)r * HEAD + c] = acc[i][j] + bias[c];
        }
    }
}

// ---------------------------------------------------------------------------
// Flash attention, fp32, online softmax.
// Block: 64 query rows (Br=64) x full head (D=64). Key tiles Bc=64.
// 256 threads, 4x4 micro-tiles for both S (64x64) and O (64x64).
// Smem: Qs[64][65], Ks[64][65] (reused as P after S), Vs[64][65].
// Stride 65 keeps the [(4t+i)*s + d] read pattern conflict-free.
// scale = 1/sqrt(DMODEL) = 1/32 exactly.
// ---------------------------------------------------------------------------
#define ATT_STRIDE 65
#define SMEM_ATTN  (3 * 64 * ATT_STRIDE * sizeof(float))   // 49920 B

__global__ __launch_bounds__(256) void attn_kernel(float* __restrict__ out)
{
    extern __shared__ float sm[];
    float* Qs = sm;                          // [64][65]
    float* Ks = sm + 64 * ATT_STRIDE;        // [64][65], reused as P
    float* Vs = sm + 2 * 64 * ATT_STRIDE;    // [64][65]

    const int b  = blockIdx.y;
    const int mt = gridDim.x - 1 - blockIdx.x;   // heavy (long) tiles first
    const int row0 = mt * 64;

    const int t  = threadIdx.x;
    const int tx = t & 15;
    const int ty = t >> 4;

    // Load Q tile once (row-major, stride 65)
    {
        const float* qg = g_q + ((size_t)b * SEQ + row0) * HEAD;
        #pragma unroll
        for (int i = t; i < 64 * 64; i += 256) {
            int r = i >> 6, d = i & 63;
            Qs[r * ATT_STRIDE + d] = qg[(size_t)r * HEAD + d];
        }
    }

    float m_i[4], l_i[4], o[4][4] = {};
    #pragma unroll
    for (int i = 0; i < 4; i++) { m_i[i] = -1e30f; l_i[i] = 0.0f; }

    const float scale = 1.0f / 32.0f;   // 1/sqrt(1024)

    for (int kt = 0; kt <= mt; kt++) {
        __syncthreads();   // previous P / V fully consumed
        const float* kg = g_k + ((size_t)b * SEQ + kt * 64) * HEAD;
        const float* vg = g_v + ((size_t)b * SEQ + kt * 64) * HEAD;
        #pragma unroll
        for (int i = t; i < 64 * 64; i += 256) {
            int r = i >> 6, d = i & 63;
            Ks[r * ATT_STRIDE + d] = kg[(size_t)r * HEAD + d];
            Vs[r * ATT_STRIDE + d] = vg[(size_t)r * HEAD + d];
        }
        __syncthreads();

        // ---- S = scale * Q K^T (4x4 per thread) ----
        float s[4][4] = {};
        #pragma unroll 16
        for (int d = 0; d < 64; d++) {
            float qv[4], kv[4];
            #pragma unroll
            for (int i = 0; i < 4; i++) qv[i] = Qs[(ty * 4 + i) * ATT_STRIDE + d];
            #pragma unroll
            for (int j = 0; j < 4; j++) kv[j] = Ks[(tx * 4 + j) * ATT_STRIDE + d];
            #pragma unroll
            for (int i = 0; i < 4; i++)
                #pragma unroll
                for (int j = 0; j < 4; j++)
                    s[i][j] += qv[i] * kv[j];
        }
        #pragma unroll
        for (int i = 0; i < 4; i++)
            #pragma unroll
            for (int j = 0; j < 4; j++)
                s[i][j] *= scale;

        // Causal mask on the diagonal tile (kt == mt ⇒ col base == row base)
        if (kt == mt) {
            #pragma unroll
            for (int i = 0; i < 4; i++)
                #pragma unroll
                for (int j = 0; j < 4; j++)
                    if (tx * 4 + j > ty * 4 + i) s[i][j] = -1e30f;
        }

        // ---- online softmax stats (reduce across the 16 tx lanes) ----
        float mx[4], rs[4], p[4][4];
        #pragma unroll
        for (int i = 0; i < 4; i++) {
            float m = s[i][0];
            #pragma unroll
            for (int j = 1; j < 4; j++) m = fmaxf(m, s[i][j]);
            #pragma unroll
            for (int off = 8; off > 0; off >>= 1)
                m = fmaxf(m, __shfl_xor_sync(0xffffffffu, m, off, 16));
            mx[i] = m;
        }
        float alpha[4];
        #pragma unroll
        for (int i = 0; i < 4; i++) {
            float m_new = fmaxf(m_i[i], mx[i]);
            alpha[i] = __expf(m_i[i] - m_new);
            m_i[i] = m_new;
            float r = 0.0f;
            #pragma unroll
            for (int j = 0; j < 4; j++) {
                p[i][j] = __expf(s[i][j] - m_new);
                r += p[i][j];
            }
            #pragma unroll
            for (int off = 8; off > 0; off >>= 1)
                r += __shfl_xor_sync(0xffffffffu, r, off, 16);
            rs[i] = r;
            l_i[i] = l_i[i] * alpha[i] + rs[i];
        }
        #pragma unroll
        for (int i = 0; i < 4; i++)
            #pragma unroll
            for (int dd = 0; dd < 4; dd++)
                o[i][dd] *= alpha[i];

        // ---- write P into the K buffer (all S reads of Ks are done) ----
        __syncthreads();
        #pragma unroll
        for (int i = 0; i < 4; i++)
            #pragma unroll
            for (int j = 0; j < 4; j++)
                Ks[(ty * 4 + i) * ATT_STRIDE + tx * 4 + j] = p[i][j];
        __syncthreads();

        // ---- O += P V (4x4 per thread over j) ----
        #pragma unroll 16
        for (int j = 0; j < 64; j++) {
            float pv[4], vv[4];
            #pragma unroll
            for (int i = 0; i < 4; i++) pv[i] = Ks[(ty * 4 + i) * ATT_STRIDE + j];
            #pragma unroll
            for (int dd = 0; dd < 4; dd++) vv[dd] = Vs[j * ATT_STRIDE + tx * 4 + dd];
            #pragma unroll
            for (int i = 0; i < 4; i++)
                #pragma unroll
                for (int dd = 0; dd < 4; dd++)
                    o[i][dd] += pv[i] * vv[dd];
        }
    }

    // Epilogue: normalize and store
    #pragma unroll
    for (int i = 0; i < 4; i++) {
        float inv_l = 1.0f / l_i[i];
        int r = row0 + ty * 4 + i;
        #pragma unroll
        for (int dd = 0; dd < 4; dd++) {
            int c = tx * 4 + dd;
            out[((size_t)b * SEQ + r) * HEAD + c] = o[i][dd] * inv_l;
        }
    }
}

// ---------------------------------------------------------------------------
// Launch
// ---------------------------------------------------------------------------
extern "C" void kernel_launch(void* const* d_in, const int* in_sizes, int n_in,
                              void* d_out, int out_size)
{
    const float* x  = (const float*)d_in[0];
    const float* Wq = (const float*)d_in[1];
    const float* bq = (const float*)d_in[2];
    const float* Wk = (const float*)d_in[3];
    const float* bk = (const float*)d_in[4];
    const float* Wv = (const float*)d_in[5];
    const float* bv = (const float*)d_in[6];
    float* out = (float*)d_out;

    (void)in_sizes; (void)n_in; (void)out_size;

    // QKV projections: 256 row-tiles x {q,k,v}
    proj_kernel<<<dim3(BT / 64, 3), 256>>>(x, Wq, bq, Wk, bk, Wv, bv);

    // Flash attention: (query tiles, batch). Needs >48KB dynamic smem.
    cudaFuncSetAttribute(attn_kernel, cudaFuncAttributeMaxDynamicSharedMemorySize,
                         (int)SMEM_ATTN);
    attn_kernel<<<dim3(SEQ / 64, BATCH), 256, SMEM_ATTN>>>(out);
}